// round 4
// baseline (speedup 1.0000x reference)
#include <cuda_runtime.h>
#include <cstdint>

#define HH 256
#define WW 256

__device__ __forceinline__ uint32_t f2tf32(float f) {
    uint32_t r;
    asm("cvt.rna.tf32.f32 %0, %1;" : "=r"(r) : "f"(f));
    return r;
}

// Pre-converted, ic-permuted weights: g_W2[chunk][tap][oc][16 icp], tf32 bits.
// icp = phi(icl) = (icl&3)*4 + (icl>>2)  -> thread tig v4-loads icp=4*tig..4*tig+3
// giving ic = tig, tig+4, tig+8, tig+12  = (s0.b0, s0.b1, s1.b0, s1.b1)
__device__ float g_W2[4 * 9 * 64 * 16];

__global__ void prep_weights(const float* __restrict__ Wt) {
    int i = blockIdx.x * 256 + threadIdx.x;   // 36864 total
    if (i >= 4 * 9 * 64 * 16) return;
    int icp   = i & 15;
    int t     = i >> 4;
    int oc    = t & 63;
    int u     = t >> 6;
    int tap   = u % 9;
    int chunk = u / 9;
    int icl   = 4 * (icp & 3) + (icp >> 2);
    int ic    = chunk * 16 + icl;
    int kh    = tap / 3;
    int kw    = tap % 3;
    float w = Wt[((oc * 64 + ic) * 3 + kh) * 3 + kw];
    g_W2[i] = __uint_as_float(f2tf32(w));
}

// SMEM: sIn[3][16][264] (tf32), sW[9][64][16] (tf32, permuted), sB[64]
#define SIN_SZ (3 * 16 * 264)
#define SW_SZ  (9 * 64 * 16)
#define SMEM_BYTES ((SIN_SZ + SW_SZ + 64) * 4)

__global__ __launch_bounds__(128, 2)
void conv_tf32_mma_kernel(const float* __restrict__ x,
                          const float* __restrict__ bias,
                          float* __restrict__ out)
{
    extern __shared__ float sm[];
    float* sIn = sm;
    float* sW  = sm + SIN_SZ;
    float* sB  = sm + SIN_SZ + SW_SZ;

    const int tid  = threadIdx.x;
    const int lane = tid & 31;
    const int wid  = tid >> 5;          // 4 warps, each 64 px x 64 oc
    const int g    = lane >> 2;
    const int tig  = lane & 3;
    const int h    = blockIdx.x;
    const int n    = blockIdx.y;
    const int px0  = wid * 64;

    if (tid < 64) sB[tid] = bias[tid];

    float c[4][8][4];
    #pragma unroll
    for (int mt = 0; mt < 4; ++mt)
        #pragma unroll
        for (int nt = 0; nt < 8; ++nt)
            #pragma unroll
            for (int r = 0; r < 4; ++r) c[mt][nt][r] = 0.0f;

    for (int chunk = 0; chunk < 4; ++chunk) {
        const int ic0 = chunk * 16;
        if (chunk) __syncthreads();

        // ---- stage input: 3 rows x 16 ic x 258 cols, tf32-rounded ----
        #pragma unroll 1
        for (int kh = 0; kh < 3; ++kh) {
            const int gh = h + kh - 1;
            #pragma unroll 1
            for (int ic = 0; ic < 16; ++ic) {
                const float* src = x + (((size_t)n * 64 + ic0 + ic) * 256 + gh) * 256;
                float* dst = sIn + kh * (16 * 264) + ic * 264;
                for (int col = tid; col < 258; col += 128) {
                    int gw = col - 1;
                    float v = 0.0f;
                    if ((unsigned)gh < 256u && (unsigned)gw < 256u) v = src[gw];
                    dst[col] = __uint_as_float(f2tf32(v));
                }
            }
        }
        // ---- stage weights: straight float4 copy of permuted block ----
        {
            const float4* src = (const float4*)(g_W2 + chunk * SW_SZ);
            float4* dst = (float4*)sW;
            #pragma unroll
            for (int i = 0; i < SW_SZ / 4 / 128; ++i)
                dst[tid + i * 128] = src[tid + i * 128];
        }
        __syncthreads();

        // ---- compute: 9 taps, B via one v4 per (tap,nt), 2 k8-steps ----
        #pragma unroll
        for (int kh = 0; kh < 3; ++kh) {
            #pragma unroll
            for (int kw = 0; kw < 3; ++kw) {
                const float* wB = sW + (kh * 3 + kw) * (64 * 16);
                float4 bv[8];
                #pragma unroll
                for (int nt = 0; nt < 8; ++nt)
                    bv[nt] = *(const float4*)(wB + (nt * 8 + g) * 16 + 4 * tig);

                #pragma unroll
                for (int s = 0; s < 2; ++s) {
                    uint32_t a[4][4];
                    #pragma unroll
                    for (int mt = 0; mt < 4; ++mt) {
                        const float* ab = sIn + kh * (16 * 264)
                                        + (s * 8 + tig) * 264 + px0 + mt * 16 + g + kw;
                        a[mt][0] = __float_as_uint(ab[0]);
                        a[mt][1] = __float_as_uint(ab[8]);
                        a[mt][2] = __float_as_uint(ab[4 * 264]);
                        a[mt][3] = __float_as_uint(ab[4 * 264 + 8]);
                    }
                    #pragma unroll
                    for (int mt = 0; mt < 4; ++mt)
                        #pragma unroll
                        for (int nt = 0; nt < 8; ++nt) {
                            uint32_t b0 = __float_as_uint(s ? bv[nt].z : bv[nt].x);
                            uint32_t b1 = __float_as_uint(s ? bv[nt].w : bv[nt].y);
                            asm volatile(
                                "mma.sync.aligned.m16n8k8.row.col.f32.tf32.tf32.f32 "
                                "{%0,%1,%2,%3}, {%4,%5,%6,%7}, {%8,%9}, {%0,%1,%2,%3};"
                                : "+f"(c[mt][nt][0]), "+f"(c[mt][nt][1]),
                                  "+f"(c[mt][nt][2]), "+f"(c[mt][nt][3])
                                : "r"(a[mt][0]), "r"(a[mt][1]),
                                  "r"(a[mt][2]), "r"(a[mt][3]),
                                  "r"(b0), "r"(b1));
                        }
                }
            }
        }
    }

    // ---- epilogue: bias + store ----
    #pragma unroll
    for (int mt = 0; mt < 4; ++mt) {
        const int px = px0 + mt * 16 + g;
        #pragma unroll
        for (int nt = 0; nt < 8; ++nt) {
            const int oc = nt * 8 + 2 * tig;
            const size_t b0 = (((size_t)n * 64 + oc) * 256 + h) * 256;
            const size_t b1 = (((size_t)n * 64 + oc + 1) * 256 + h) * 256;
            out[b0 + px]     = c[mt][nt][0] + sB[oc];
            out[b1 + px]     = c[mt][nt][1] + sB[oc + 1];
            out[b0 + px + 8] = c[mt][nt][2] + sB[oc];
            out[b1 + px + 8] = c[mt][nt][3] + sB[oc + 1];
        }
    }
}

extern "C" void kernel_launch(void* const* d_in, const int* in_sizes, int n_in,
                              void* d_out, int out_size)
{
    const float* x  = (const float*)d_in[0];
    const float* Wt = (const float*)d_in[1];
    const float* b  = (const float*)d_in[2];
    float* out = (float*)d_out;

    cudaFuncSetAttribute(conv_tf32_mma_kernel,
                         cudaFuncAttributeMaxDynamicSharedMemorySize, SMEM_BYTES);

    prep_weights<<<144, 256>>>(Wt);

    dim3 grid(HH, 16);   // (h, n) = 4096 CTAs, M=256 px per CTA
    conv_tf32_mma_kernel<<<grid, 128, SMEM_BYTES>>>(x, b, out);
}

// round 5
// speedup vs baseline: 5.2407x; 5.2407x over previous
#include <cuda_runtime.h>
#include <cuda_fp16.h>
#include <cstdint>

#define HH 256
#define WW 256

// ============================ weight prep =====================================
// g_W3[chunk][tap][oc][psi] : half2 = (W[ic0+2p], W[ic0+2p+1]), psi(p)=(p&3)*2+(p>>2)
// so an LDS.64 at u32 offset 2*tig yields {pair tig, pair tig+4} = (b0, b1).
__device__ uint32_t g_W3[4 * 9 * 64 * 8];

__global__ void prep_weights(const float* __restrict__ Wt) {
    int i = blockIdx.x * 256 + threadIdx.x;   // 18432 total
    if (i >= 4 * 9 * 64 * 8) return;
    int q     = i & 7;
    int oc    = (i >> 3) & 63;
    int tap   = (i >> 9) % 9;
    int chunk = i / (512 * 9);
    int p     = (q >> 1) + (q & 1) * 4;       // inverse psi
    int kh    = tap / 3;
    int kw    = tap % 3;
    int ic    = chunk * 16 + 2 * p;
    float w0 = Wt[((oc * 64 + ic) * 3 + kh) * 3 + kw];
    float w1 = Wt[((oc * 64 + ic + 1) * 3 + kh) * 3 + kw];
    __half2 hv = __floats2half2_rn(w0, w1);   // lo = even ic (k=2*tig)
    g_W3[i] = *(uint32_t*)&hv;
}

// SMEM (u32 units): sIn2[3][8][264] = 6336, sW[9][64][8] = 4608, sB[64]
#define SIN_U32 (3 * 8 * 264)
#define SW_U32  (9 * 64 * 8)
#define SMEM_BYTES ((SIN_U32 + SW_U32 + 64) * 4)

__global__ __launch_bounds__(256, 2)
void conv_f16_mma_kernel(const float* __restrict__ x,
                         const float* __restrict__ bias,
                         float* __restrict__ out)
{
    extern __shared__ uint32_t sm[];
    uint32_t* sIn = sm;                   // [kh][p][col] col stride 264
    uint32_t* sW  = sm + SIN_U32;         // [tap][oc][psi]
    float*    sB  = (float*)(sm + SIN_U32 + SW_U32);

    const int tid  = threadIdx.x;
    const int lane = tid & 31;
    const int wid  = tid >> 5;            // 8 warps: 4 along px, 2 along oc
    const int g    = lane >> 2;
    const int tig  = lane & 3;
    const int h    = blockIdx.x;
    const int n    = blockIdx.y;
    const int px0  = (wid >> 1) * 64;
    const int oc0  = (wid & 1) * 32;

    if (tid < 64) sB[tid] = bias[tid];

    float c[4][4][4];
    #pragma unroll
    for (int mt = 0; mt < 4; ++mt)
        #pragma unroll
        for (int nt = 0; nt < 4; ++nt)
            #pragma unroll
            for (int r = 0; r < 4; ++r) c[mt][nt][r] = 0.0f;

    for (int chunk = 0; chunk < 4; ++chunk) {
        const int ic0 = chunk * 16;
        if (chunk) __syncthreads();

        // ---- stage input: 3 rows x 8 ic-pairs x 258 cols as half2 ----
        for (int i = tid; i < 3 * 8 * 258; i += 256) {
            int col = i % 258;
            int t2  = i / 258;
            int p   = t2 & 7;
            int kh  = t2 >> 3;
            int gh  = h + kh - 1;
            int gw  = col - 1;
            float v0 = 0.0f, v1 = 0.0f;
            if ((unsigned)gh < 256u && (unsigned)gw < 256u) {
                const float* base = x + (((size_t)n * 64 + ic0 + 2 * p) * 256 + gh) * 256 + gw;
                v0 = base[0];
                v1 = base[256 * 256];
            }
            __half2 hv = __floats2half2_rn(v0, v1);
            sIn[kh * (8 * 264) + p * 264 + col] = *(uint32_t*)&hv;
        }
        // ---- stage weights: vector copy of pre-packed chunk (18432 B) ----
        {
            const uint4* src = (const uint4*)(g_W3 + chunk * SW_U32);
            uint4* dst = (uint4*)sW;
            for (int i = tid; i < SW_U32 / 4; i += 256)
                dst[i] = src[i];
        }
        __syncthreads();

        // ---- compute: 9 taps x (4 mt x 4 nt) m16n8k16 ----
        #pragma unroll
        for (int kh = 0; kh < 3; ++kh) {
            #pragma unroll
            for (int kw = 0; kw < 3; ++kw) {
                const uint32_t* wB = sW + (kh * 3 + kw) * (64 * 8);
                uint32_t b[4][2];
                #pragma unroll
                for (int nt = 0; nt < 4; ++nt) {
                    // LDS.64: psi 2*tig, 2*tig+1 -> pairs tig, tig+4
                    const uint2 bv = *(const uint2*)(wB + (oc0 + nt * 8 + g) * 8 + 2 * tig);
                    b[nt][0] = bv.x;
                    b[nt][1] = bv.y;
                }
                #pragma unroll
                for (int mt = 0; mt < 4; ++mt) {
                    const uint32_t* ab = sIn + kh * (8 * 264) + px0 + mt * 16 + g + kw;
                    uint32_t a0 = ab[tig * 264];
                    uint32_t a1 = ab[tig * 264 + 8];
                    uint32_t a2 = ab[(tig + 4) * 264];
                    uint32_t a3 = ab[(tig + 4) * 264 + 8];
                    #pragma unroll
                    for (int nt = 0; nt < 4; ++nt)
                        asm volatile(
                            "mma.sync.aligned.m16n8k16.row.col.f32.f16.f16.f32 "
                            "{%0,%1,%2,%3}, {%4,%5,%6,%7}, {%8,%9}, {%0,%1,%2,%3};"
                            : "+f"(c[mt][nt][0]), "+f"(c[mt][nt][1]),
                              "+f"(c[mt][nt][2]), "+f"(c[mt][nt][3])
                            : "r"(a0), "r"(a1), "r"(a2), "r"(a3),
                              "r"(b[nt][0]), "r"(b[nt][1]));
                }
            }
        }
    }

    // ---- epilogue: bias + store ----
    #pragma unroll
    for (int mt = 0; mt < 4; ++mt) {
        const int px = px0 + mt * 16 + g;
        #pragma unroll
        for (int nt = 0; nt < 4; ++nt) {
            const int oc = oc0 + nt * 8 + 2 * tig;
            const size_t b0 = (((size_t)n * 64 + oc) * 256 + h) * 256;
            const size_t b1 = (((size_t)n * 64 + oc + 1) * 256 + h) * 256;
            out[b0 + px]     = c[mt][nt][0] + sB[oc];
            out[b1 + px]     = c[mt][nt][1] + sB[oc + 1];
            out[b0 + px + 8] = c[mt][nt][2] + sB[oc];
            out[b1 + px + 8] = c[mt][nt][3] + sB[oc + 1];
        }
    }
}

extern "C" void kernel_launch(void* const* d_in, const int* in_sizes, int n_in,
                              void* d_out, int out_size)
{
    const float* x  = (const float*)d_in[0];
    const float* Wt = (const float*)d_in[1];
    const float* b  = (const float*)d_in[2];
    float* out = (float*)d_out;

    cudaFuncSetAttribute(conv_f16_mma_kernel,
                         cudaFuncAttributeMaxDynamicSharedMemorySize, SMEM_BYTES);

    prep_weights<<<72, 256>>>(Wt);

    dim3 grid(HH, 16);   // (h, n): 4096 CTAs, 256 px x 64 oc each
    conv_f16_mma_kernel<<<grid, 256, SMEM_BYTES>>>(x, b, out);
}